// round 5
// baseline (speedup 1.0000x reference)
#include <cuda_runtime.h>
#include <cuda_bf16.h>
#include <cstdint>

#define VOCAB  50257
#define VPAD   50304          // 393 * 128
#define DMODEL 768
#define MTOT   4096           // B*S
#define SEQ    2048

#define BM 128
#define BN 128
#define BK 64
#define STAGES 3
#define NKC (DMODEL / BK)                 // 12
#define TILE_BYTES (BM * BK * 2)          // 16384
#define STAGE_BYTES (2 * TILE_BYTES)      // 32768 (A + B)
#define SMEM_BYTES (STAGES * STAGE_BYTES) // 98304

// Scratch (static device globals — allocation-guard safe)
__device__ __nv_bfloat16 g_wt[(size_t)VPAD * DMODEL];   // W^T [v][k], rows >= VOCAB zeroed
__device__ __nv_bfloat16 g_hid[(size_t)MTOT * DMODEL];  // hidden [m][k]

// ---------------- helpers ----------------
__device__ __forceinline__ uint32_t smem_u32(const void* p) {
    return (uint32_t)__cvta_generic_to_shared(p);
}

__device__ __forceinline__ void ldsm4(uint32_t* r, uint32_t addr) {
    asm volatile("ldmatrix.sync.aligned.m8n8.x4.shared.b16 {%0,%1,%2,%3}, [%4];"
                 : "=r"(r[0]), "=r"(r[1]), "=r"(r[2]), "=r"(r[3]) : "r"(addr));
}

__device__ __forceinline__ void mma16816(float* c, const uint32_t* a, uint32_t b0, uint32_t b1) {
    asm volatile(
        "mma.sync.aligned.m16n8k16.row.col.f32.bf16.bf16.f32 "
        "{%0,%1,%2,%3}, {%4,%5,%6,%7}, {%8,%9}, {%0,%1,%2,%3};"
        : "+f"(c[0]), "+f"(c[1]), "+f"(c[2]), "+f"(c[3])
        : "r"(a[0]), "r"(a[1]), "r"(a[2]), "r"(a[3]), "r"(b0), "r"(b1));
}

__device__ __forceinline__ void cp16(uint32_t dst, const void* src) {
    asm volatile("cp.async.cg.shared.global [%0], [%1], 16;" :: "r"(dst), "l"(src));
}

// ---------------- prep 1: hidden = bf16(wte[id] + wpe[pos]) ----------------
// wte/wpe arrive as int32 (harness widens int8 inputs), values in [-127,127].
__global__ void embed_kernel(const int* __restrict__ ids,
                             const int* __restrict__ wte,
                             const int* __restrict__ wpe) {
    int m  = blockIdx.x;              // 0..4095
    int k4 = threadIdx.x * 4;         // 192 threads * 4 = 768
    int id  = ids[m];
    int pos = m & (SEQ - 1);
    int4 a = *(const int4*)(wte + (size_t)id  * DMODEL + k4);
    int4 p = *(const int4*)(wpe + (size_t)pos * DMODEL + k4);
    __nv_bfloat16 h[4];
    h[0] = __float2bfloat16((float)(a.x + p.x));
    h[1] = __float2bfloat16((float)(a.y + p.y));
    h[2] = __float2bfloat16((float)(a.z + p.z));
    h[3] = __float2bfloat16((float)(a.w + p.w));
    *(uint2*)(g_hid + (size_t)m * DMODEL + k4) = *(uint2*)h;
}

// ---------------- prep 2: W^T bf16 [VPAD,768] from int32 [768,VOCAB] ----------------
__global__ void packw_kernel(const int* __restrict__ w) {
    __shared__ __nv_bfloat16 tile[32][33];
    int v0 = blockIdx.x * 32;   // vocab
    int k0 = blockIdx.y * 32;   // dmodel
    int tx = threadIdx.x, ty = threadIdx.y;  // (32, 8)
    #pragma unroll
    for (int j = 0; j < 32; j += 8) {
        int v = v0 + tx;
        int val = (v < VOCAB) ? w[(size_t)(k0 + ty + j) * VOCAB + v] : 0;
        tile[ty + j][tx] = __float2bfloat16((float)val);
    }
    __syncthreads();
    #pragma unroll
    for (int j = 0; j < 32; j += 8) {
        int v = v0 + ty + j;  // < VPAD
        g_wt[(size_t)v * DMODEL + (k0 + tx)] = tile[tx][ty + j];
    }
}

// ---------------- main GEMM: 128x128 per CTA, mma.sync bf16 ----------------
__global__ void __launch_bounds__(256)
gemm_kernel(const int* __restrict__ bias, float* __restrict__ out) {
    extern __shared__ unsigned char smem[];
    const int tid  = threadIdx.x;
    const int wid  = tid >> 5;
    const int lane = tid & 31;
    const int m0 = blockIdx.x * BM;
    const int n0 = blockIdx.y * BN;
    const int wm = (wid & 3) * 32;   // warp m offset within CTA tile
    const int wn = (wid >> 2) * 64;  // warp n offset within CTA tile

    const uint32_t sbase = smem_u32(smem);
    const __nv_bfloat16* gA = g_hid + (size_t)m0 * DMODEL;
    const __nv_bfloat16* gB = g_wt  + (size_t)n0 * DMODEL;

    // Per-thread load coords: 4 x 16B chunks each for A and B per stage
    int lco[4];
    const __nv_bfloat16* lsa[4];
    const __nv_bfloat16* lsb[4];
    #pragma unroll
    for (int i = 0; i < 4; i++) {
        int idx = tid + i * 256;
        int r = idx >> 3, c = idx & 7;
        lco[i] = r * 128 + ((c ^ (r & 7)) << 4);
        lsa[i] = gA + (size_t)r * DMODEL + c * 8;
        lsb[i] = gB + (size_t)r * DMODEL + c * 8;
    }

    float acc[2][8][4];
    #pragma unroll
    for (int i = 0; i < 2; i++)
        #pragma unroll
        for (int j = 0; j < 8; j++)
            #pragma unroll
            for (int q = 0; q < 4; q++) acc[i][j][q] = 0.f;

    // ---- prefetch STAGES-1 stages ----
    #pragma unroll
    for (int s = 0; s < STAGES - 1; s++) {
        uint32_t dstA = sbase + s * STAGE_BYTES;
        uint32_t dstB = dstA + TILE_BYTES;
        #pragma unroll
        for (int i = 0; i < 4; i++) {
            cp16(dstA + lco[i], lsa[i] + s * BK);
            cp16(dstB + lco[i], lsb[i] + s * BK);
        }
        asm volatile("cp.async.commit_group;");
    }

    const int lrow = lane & 15;
    const int lhi  = lane >> 4;

    for (int kc = 0; kc < NKC; kc++) {
        asm volatile("cp.async.wait_group %0;" :: "n"(STAGES - 2));
        __syncthreads();

        const int st = kc % STAGES;
        const uint32_t baseA = sbase + st * STAGE_BYTES;
        const uint32_t baseB = baseA + TILE_BYTES;

        #pragma unroll
        for (int kk = 0; kk < 4; kk++) {
            const int c = kk * 2 + lhi;  // 16B-chunk col
            uint32_t a[2][4], b[4][4];
            #pragma unroll
            for (int f = 0; f < 2; f++) {
                int r = wm + f * 16 + lrow;
                ldsm4(a[f], baseA + r * 128 + ((c ^ (r & 7)) << 4));
            }
            #pragma unroll
            for (int f = 0; f < 4; f++) {
                int r = wn + f * 16 + lrow;
                ldsm4(b[f], baseB + r * 128 + ((c ^ (r & 7)) << 4));
            }
            #pragma unroll
            for (int i = 0; i < 2; i++)
                #pragma unroll
                for (int f = 0; f < 4; f++) {
                    mma16816(acc[i][2 * f + 0], a[i], b[f][0], b[f][2]);
                    mma16816(acc[i][2 * f + 1], a[i], b[f][1], b[f][3]);
                }
        }

        const int nk = kc + STAGES - 1;
        if (nk < NKC) {
            const int st2 = nk % STAGES;
            uint32_t dstA = sbase + st2 * STAGE_BYTES;
            uint32_t dstB = dstA + TILE_BYTES;
            #pragma unroll
            for (int i = 0; i < 4; i++) {
                cp16(dstA + lco[i], lsa[i] + nk * BK);
                cp16(dstB + lco[i], lsb[i] + nk * BK);
            }
        }
        asm volatile("cp.async.commit_group;");
    }

    // ---- epilogue: float32 out = round(acc) + bias ----
    // Scalar 4B stores: rows are only 4B-aligned (VOCAB odd).
    #pragma unroll
    for (int i = 0; i < 2; i++) {
        const int r = m0 + wm + i * 16 + (lane >> 2);
        float* row0 = out + (size_t)r * VOCAB;
        float* row1 = row0 + (size_t)8 * VOCAB;
        #pragma unroll
        for (int j = 0; j < 8; j++) {
            const int col = n0 + wn + j * 8 + ((lane & 3) << 1);
            if (col < VOCAB) {
                const int b0 = bias[col];
                row0[col] = (float)(__float2int_rn(acc[i][j][0]) + b0);
                row1[col] = (float)(__float2int_rn(acc[i][j][2]) + b0);
            }
            if (col + 1 < VOCAB) {
                const int b1 = bias[col + 1];
                row0[col + 1] = (float)(__float2int_rn(acc[i][j][1]) + b1);
                row1[col + 1] = (float)(__float2int_rn(acc[i][j][3]) + b1);
            }
        }
    }
}

// ---------------- launch ----------------
extern "C" void kernel_launch(void* const* d_in, const int* in_sizes, int n_in,
                              void* d_out, int out_size) {
    const int* ids  = (const int*)d_in[0];   // [2,2048] int32
    const int* wte  = (const int*)d_in[1];   // [50257,768] int8 widened to int32
    const int* wpe  = (const int*)d_in[2];   // [2048,768] int8 widened to int32
    const int* w    = (const int*)d_in[3];   // [768,50257] int32
    const int* bias = (const int*)d_in[4];   // [50257] int32
    float* out = (float*)d_out;              // [2,2048,50257] float32

    cudaFuncSetAttribute(gemm_kernel, cudaFuncAttributeMaxDynamicSharedMemorySize, SMEM_BYTES);

    embed_kernel<<<MTOT, DMODEL / 4>>>(ids, wte, wpe);
    packw_kernel<<<dim3(VPAD / 32, DMODEL / 32), dim3(32, 8)>>>(w);
    gemm_kernel<<<dim3(MTOT / BM, VPAD / BN), 256, SMEM_BYTES>>>(bias, out);
}